// round 14
// baseline (speedup 1.0000x reference)
#include <cuda_runtime.h>
#include <cuda_fp16.h>
#include <cstdint>

#define B_  16
#define T_  512
#define K_  8
#define NI_ 256
#define UN_ 256
#define G_  1024   // 4*UNITS

// Hoisted x@W + b, GATE-INTERLEAVED: col = 4*u + g  (u=unit 0..255, g=gate).
__device__ float g_xw[(size_t)B_ * T_ * K_ * G_];
// Progress flags: g_flags[k][chunk] counts completed GEMM blocks (target 128).
__device__ unsigned int g_flags[K_][8];

__device__ __forceinline__ uint32_t smem_u32(const void* p) {
    uint32_t a;
    asm("{ .reg .u64 t; cvta.to.shared.u64 t, %1; cvt.u32.u64 %0, t; }" : "=r"(a) : "l"(p));
    return a;
}
__device__ __forceinline__ float hsig(float v) {
    return fminf(fmaxf(fmaf(v, 0.2f, 0.5f), 0.0f), 1.0f);
}
// Branchless tanh: (e^2x - 1)/(e^2x + 1), clamped. On the h->h critical chain.
__device__ __forceinline__ float ftanh(float x) {
    float xc = fminf(fmaxf(x, -9.0f), 9.0f);
    float e = __expf(2.0f * xc);
    return __fdividef(e - 1.0f, e + 1.0f);
}

#define LDSM4(r0, r1, r2, r3, addr)                                              \
    asm volatile("ldmatrix.sync.aligned.m8n8.x4.shared.b16 {%0,%1,%2,%3}, [%4];" \
                 : "=r"(r0), "=r"(r1), "=r"(r2), "=r"(r3) : "r"(addr))
#define LDSM2(r0, r1, addr)                                                      \
    asm volatile("ldmatrix.sync.aligned.m8n8.x2.shared.b16 {%0,%1}, [%2];"       \
                 : "=r"(r0), "=r"(r1) : "r"(addr))
#define LDSM4T(r0, r1, r2, r3, addr)                                             \
    asm volatile("ldmatrix.sync.aligned.m8n8.x4.trans.shared.b16 {%0,%1,%2,%3}, [%4];" \
                 : "=r"(r0), "=r"(r1), "=r"(r2), "=r"(r3) : "r"(addr))
#define MMA16816(d, a0, a1, a2, a3, b0, b1)                                      \
    asm volatile("mma.sync.aligned.m16n8k16.row.col.f32.f16.f16.f32 "            \
                 "{%0,%1,%2,%3}, {%4,%5,%6,%7}, {%8,%9}, {%0,%1,%2,%3};"         \
                 : "+f"(d[0]), "+f"(d[1]), "+f"(d[2]), "+f"(d[3])                \
                 : "r"(a0), "r"(a1), "r"(a2), "r"(a3), "r"(b0), "r"(b1))

#define MBAR_WAIT(addr, ph) do {                                                          \
    uint32_t _done;                                                                       \
    asm volatile("{ .reg .pred p; mbarrier.try_wait.parity.acquire.cta.shared::cta.b64 "  \
                 "p, [%1], %2; selp.b32 %0,1,0,p; }"                                      \
                 : "=r"(_done) : "r"(addr), "r"(ph) : "memory");                          \
    while (!_done) {                                                                      \
        asm volatile("{ .reg .pred p; mbarrier.try_wait.parity.acquire.cta.shared::cta.b64 " \
                     "p, [%1], %2, 0x989680; selp.b32 %0,1,0,p; }"                        \
                     : "=r"(_done) : "r"(addr), "r"(ph) : "memory");                      \
    }                                                                                     \
} while (0)

// ---------------------------------------------------------------------------
// Kernel 1 (HMMA): x@W + b into g_xw, col = 4u+g. M-tile 64 (2 blocks/SM),
// 8 chunk-major t-chunks of 64 steps, release completion flags. (R13-proven.)
// ---------------------------------------------------------------------------
#define AP 264
#define BP 136
#define SM1_A 0
#define SM1_B (64 * AP * 2)
#define SM1_TOT (SM1_B + 256 * BP * 2)

__global__ __launch_bounds__(256, 2) void gemm_xw_hmma(
    const float* __restrict__ x, const float* __restrict__ W,
    const float* __restrict__ bias)
{
    extern __shared__ char smem[];
    const uint32_t sb = smem_u32(smem);
    const int tid = threadIdx.x, w = tid >> 5, l = tid & 31;
    const int nb    = blockIdx.x;
    const int k     = blockIdx.y >> 4;
    const int cell  = blockIdx.y & 15;
    const int chunk = blockIdx.z;
    const int bm    = (cell * 8 + chunk) * 64;

    half* As = (half*)(smem + SM1_A);
    for (int idx = tid; idx < 64 * 64; idx += 256) {
        int r = idx >> 6, c4 = idx & 63;
        float4 v = *(const float4*)(x + ((size_t)(bm + r) * K_ + k) * NI_ + c4 * 4);
        __half2 h01 = __floats2half2_rn(v.x, v.y);
        __half2 h23 = __floats2half2_rn(v.z, v.w);
        uint2 pk = make_uint2(*(uint32_t*)&h01, *(uint32_t*)&h23);
        *(uint2*)(As + r * AP + c4 * 4) = pk;
    }
    half* Bs = (half*)(smem + SM1_B);
    for (int idx = tid; idx < 256 * 128; idx += 256) {
        int i = idx >> 7, np = idx & 127;
        int u = np >> 2, g = np & 3;
        Bs[i * BP + np] = __float2half_rn(
            W[((size_t)k * NI_ + i) * G_ + g * 256 + nb * 32 + u]);
    }
    __syncthreads();

    const int wm = w >> 2, wn = w & 3;
    float acc[2][4][4];
#pragma unroll
    for (int a = 0; a < 2; a++)
#pragma unroll
        for (int b = 0; b < 4; b++)
#pragma unroll
            for (int e = 0; e < 4; e++) acc[a][b][e] = 0.0f;

#pragma unroll
    for (int ks = 0; ks < 16; ks++) {
        uint32_t af[2][4], bf[2][4];
#pragma unroll
        for (int ma = 0; ma < 2; ma++) {
            uint32_t aaddr = sb + SM1_A
                + (uint32_t)(wm * 32 + ma * 16 + (l & 15)) * (AP * 2)
                + (uint32_t)ks * 32 + (uint32_t)(l >> 4) * 16;
            LDSM4(af[ma][0], af[ma][1], af[ma][2], af[ma][3], aaddr);
        }
#pragma unroll
        for (int n2 = 0; n2 < 2; n2++) {
            uint32_t baddr = sb + SM1_B
                + (uint32_t)(ks * 16 + ((l >> 3) & 1) * 8 + (l & 7)) * (BP * 2)
                + (uint32_t)(wn * 32 + n2 * 16 + (l >> 4) * 8) * 2;
            LDSM4T(bf[n2][0], bf[n2][1], bf[n2][2], bf[n2][3], baddr);
        }
#pragma unroll
        for (int ma = 0; ma < 2; ma++) {
            MMA16816(acc[ma][0], af[ma][0], af[ma][1], af[ma][2], af[ma][3], bf[0][0], bf[0][1]);
            MMA16816(acc[ma][1], af[ma][0], af[ma][1], af[ma][2], af[ma][3], bf[0][2], bf[0][3]);
            MMA16816(acc[ma][2], af[ma][0], af[ma][1], af[ma][2], af[ma][3], bf[1][0], bf[1][1]);
            MMA16816(acc[ma][3], af[ma][0], af[ma][1], af[ma][2], af[ma][3], bf[1][2], bf[1][3]);
        }
    }

#pragma unroll
    for (int nt = 0; nt < 4; nt++) {
        const int np = wn * 32 + nt * 8 + (l & 3) * 2;
        const int u = np >> 2, g = np & 3;
        const float b0 = __ldg(bias + (size_t)k * G_ + g * 256 + nb * 32 + u);
        const float b1 = __ldg(bias + (size_t)k * G_ + (g + 1) * 256 + nb * 32 + u);
#pragma unroll
        for (int ma = 0; ma < 2; ma++) {
            const int m0 = bm + wm * 32 + ma * 16 + (l >> 2);
            float* p0 = g_xw + ((size_t)m0 * K_ + k) * G_ + nb * 128 + np;
            float* p1 = g_xw + ((size_t)(m0 + 8) * K_ + k) * G_ + nb * 128 + np;
            *(float2*)p0 = make_float2(acc[ma][nt][0] + b0, acc[ma][nt][1] + b1);
            *(float2*)p1 = make_float2(acc[ma][nt][2] + b0, acc[ma][nt][3] + b1);
        }
    }

    __threadfence();
    __syncthreads();
    if (tid == 0)
        asm volatile("red.release.gpu.global.add.u32 [%0], %1;"
                     :: "l"(&g_flags[k][chunk]), "r"(1u) : "memory");
}

// ---------------------------------------------------------------------------
// Kernel 2: recurrence v7. v6 + (a) local-slab ks MMA issued BEFORE the
// mbarrier wait (slab `rank` is locally written, visible since the previous
// phase's __syncthreads; only 3 remote slabs are mbar-gated), (b) 4 accum
// chains of depth 4, (c) out stores after bulk issue.
// ---------------------------------------------------------------------------
#define UTP   264
#define SLAB  2304
#define HALFB 1152
#define HBUF  (4 * SLAB)
#define TXH   (3u * HALFB)
#define OFF_H   0
#define OFF_STG (2 * HBUF)
#define OFF_MB  (OFF_STG + 2 * SLAB)
#define OFF_UT  (OFF_MB + 128)
#define SM2_TOT (OFF_UT + 256 * UTP * 2)

__global__ __launch_bounds__(512, 1) __cluster_dims__(4, 1, 1)
void lstm_rec_v7(const float* __restrict__ U, float* __restrict__ out)
{
    extern __shared__ char smem[];
    const uint32_t sb = smem_u32(smem);
    const int tid = threadIdx.x, w = tid >> 5, l = tid & 31;
    const int k = blockIdx.x >> 2;
    uint32_t rank;
    asm("mov.u32 %0, %%cluster_ctarank;" : "=r"(rank));

    {
        const int j = tid >> 1, hf = tid & 1;
        const int wq = j >> 4, rr = j & 15;
        const int uloc = 4 * wq + (rr & 3), g = rr >> 2;
        const float* up = U + (size_t)k * NI_ * G_ + g * 256 + (int)rank * 64 + uloc;
        half* uts = (half*)(smem + OFF_UT) + (size_t)j * UTP;
        for (int i = hf * 128; i < hf * 128 + 128; i++)
            uts[i] = __float2half_rn(up[(size_t)i * G_]);
    }
    for (int idx = tid; idx < HBUF / 4; idx += 512)
        ((uint32_t*)(smem + OFF_H))[idx] = 0u;
    if (tid == 0) {
#pragma unroll
        for (int b = 0; b < 4; b++)
            asm volatile("mbarrier.init.shared.b64 [%0], %1;"
                         :: "r"(sb + OFF_MB + b * 8), "r"(1u) : "memory");
        asm volatile("mbarrier.arrive.expect_tx.shared.b64 _, [%0], %1;"
                     :: "r"(sb + OFF_MB + 16), "r"(TXH) : "memory");
        asm volatile("mbarrier.arrive.expect_tx.shared.b64 _, [%0], %1;"
                     :: "r"(sb + OFF_MB + 24), "r"(TXH) : "memory");
    }
    __syncthreads();

    uint32_t Af[16][4];
    {
        const uint32_t abase = sb + OFF_UT
            + (uint32_t)(16 * w + (l & 15)) * (UTP * 2) + (uint32_t)(l >> 4) * 16;
#pragma unroll
        for (int ks = 0; ks < 16; ks++)
            LDSM4(Af[ks][0], Af[ks][1], Af[ks][2], Af[ks][3], abase + ks * 32);
    }

    asm volatile("barrier.cluster.arrive.aligned;" ::: "memory");
    asm volatile("barrier.cluster.wait.aligned;" ::: "memory");

    const bool lo16 = (l < 16);
    const int  uloc = 4 * w + ((l >> 2) & 3);
    const int  cell0 = 2 * (l & 3) + (lo16 ? 0 : 1);
    const int  colx = 4 * ((int)rank * 64 + uloc);
    const uint32_t aHalf = sb + OFF_H + (uint32_t)(l & 7) * 144 + (uint32_t)((l >> 3) & 1) * 16;
    const float* xw0p = g_xw + ((size_t)cell0 * T_ * K_ + k) * G_ + colx;
    const float* xw1p = g_xw + ((size_t)(cell0 + 8) * T_ * K_ + k) * G_ + colx;
    const bool sender = ((l >> 2) & 1) == 0;
    const int ksOwn = (int)rank * 4;        // ks indices reading our local slab
    float c0 = 0.0f, c1 = 0.0f;
    int phA0 = 0, phA1 = 0, phB0 = 0, phB1 = 0;

    for (int t = 0; t < T_; t++) {
        const int p = t & 1;
        const uint32_t mbA = sb + OFF_MB + (uint32_t)p * 16;
        const uint32_t mbB = mbA + 8;

        if ((t & 63) == 0) {
            const int ch = t >> 6;
            unsigned int v;
            do {
                asm volatile("ld.acquire.gpu.global.u32 %0, [%1];"
                             : "=r"(v) : "l"(&g_flags[k][ch]) : "memory");
                if (v < 128u) __nanosleep(1000);
            } while (v < 128u);
        }

        float4 xwa = __ldcg((const float4*)(xw0p + (size_t)t * (K_ * G_)));
        float4 xwb = __ldcg((const float4*)(xw1p + (size_t)t * (K_ * G_)));

        // ================= PHASE A : cells 0-7 =================
        float dc[4][4];
#pragma unroll
        for (int q = 0; q < 4; q++)
#pragma unroll
            for (int e = 0; e < 4; e++) dc[q][e] = 0.0f;
        {
            const uint32_t hA = aHalf + (uint32_t)p * HBUF;
            // Local slab ks first (no wait needed: written locally, visible
            // since previous phase's __syncthreads). 4 independent chains.
#pragma unroll
            for (int q = 0; q < 4; q++) {
                const int ks = ksOwn + q;
                uint32_t b0, b1;
                LDSM2(b0, b1, hA + (uint32_t)(ks >> 2) * SLAB + (uint32_t)(ks & 3) * 32);
                MMA16816(dc[q], Af[ks][0], Af[ks][1], Af[ks][2], Af[ks][3], b0, b1);
            }
            // Wait for the 3 remote slabs, then arm for the next fill.
            if (t > 0) {
                if (p) { MBAR_WAIT(mbA, (uint32_t)phA1); phA1 ^= 1; }
                else   { MBAR_WAIT(mbA, (uint32_t)phA0); phA0 ^= 1; }
            }
            if (tid == 0)
                asm volatile("mbarrier.arrive.expect_tx.shared.b64 _, [%0], %1;"
                             :: "r"(mbA), "r"(TXH) : "memory");
            // Remaining 12 ks, round-robin over the 4 chains.
            int q = 0;
#pragma unroll
            for (int ks = 0; ks < 16; ks++) {
                if (ks >= ksOwn && ks < ksOwn + 4) continue;
                uint32_t b0, b1;
                LDSM2(b0, b1, hA + (uint32_t)(ks >> 2) * SLAB + (uint32_t)(ks & 3) * 32);
                MMA16816(dc[q & 3], Af[ks][0], Af[ks][1], Af[ks][2], Af[ks][3], b0, b1);
                q++;
            }
        }
        float dLo[4];
#pragma unroll
        for (int e = 0; e < 4; e++)
            dLo[e] = (dc[0][e] + dc[1][e]) + (dc[2][e] + dc[3][e]);

        float xa = __shfl_xor_sync(0xFFFFFFFFu, lo16 ? dLo[1] : dLo[0], 16);
        float xb = __shfl_xor_sync(0xFFFFFFFFu, lo16 ? dLo[3] : dLo[2], 16);
        float zA0, zA1, zA2, zA3;
        if (lo16) { zA0 = dLo[0]; zA1 = xa;     zA2 = dLo[2]; zA3 = xb;     }
        else      { zA0 = xa;     zA1 = dLo[1]; zA2 = xb;     zA3 = dLo[3]; }

        float av0 = ftanh(zA0 + xwa.x);
        float iv0 = hsig (zA1 + xwa.y);
        float fv0 = hsig (zA2 + xwa.z);
        float ov0 = hsig (zA3 + xwa.w);
        c0 = fmaf(fv0, c0, av0 * iv0);
        float h0 = ov0 * ftanh(c0);

        float q0 = __shfl_xor_sync(0xFFFFFFFFu, h0, 4);
        if (sender) {
            __half2 v = __floats2half2_rn(h0, q0);
            const uint32_t off = (uint32_t)cell0 * 144 + (uint32_t)uloc * 2;
            *(__half2*)(smem + OFF_STG + p * SLAB + off) = v;
            *(__half2*)(smem + OFF_H + (p ^ 1) * HBUF + rank * SLAB + off) = v;
        }

        __syncthreads();
        if (tid == 0) {
            asm volatile("fence.proxy.async;" ::: "memory");
            const uint32_t src  = sb + OFF_STG + (uint32_t)p * SLAB;
            const uint32_t dstL = sb + OFF_H + (uint32_t)(p ^ 1) * HBUF + rank * SLAB;
            const uint32_t mbL  = sb + OFF_MB + (uint32_t)(p ^ 1) * 16;
#pragma unroll
            for (int peer = 0; peer < 4; peer++) {
                if (peer == (int)rank) continue;
                uint32_t dstR, mbR;
                asm("mapa.shared::cluster.u32 %0, %1, %2;" : "=r"(dstR) : "r"(dstL), "r"(peer));
                asm("mapa.shared::cluster.u32 %0, %1, %2;" : "=r"(mbR)  : "r"(mbL),  "r"(peer));
                asm volatile(
                    "cp.async.bulk.shared::cluster.shared::cta.mbarrier::complete_tx::bytes "
                    "[%0], [%1], %2, [%3];"
                    :: "r"(dstR), "r"(src), "r"((uint32_t)HALFB), "r"(mbR) : "memory");
            }
        }
        // Global out store AFTER the bulk departs (off the exchange path).
        out[(((size_t)cell0 * T_ + t) * K_ + k) * UN_ + (size_t)rank * 64 + uloc] = h0;

        // ================= PHASE B : cells 8-15 =================
        float ec[4][4];
#pragma unroll
        for (int q = 0; q < 4; q++)
#pragma unroll
            for (int e = 0; e < 4; e++) ec[q][e] = 0.0f;
        {
            const uint32_t hB = aHalf + (uint32_t)p * HBUF + 8u * 144u;
#pragma unroll
            for (int q = 0; q < 4; q++) {
                const int ks = ksOwn + q;
                uint32_t b0, b1;
                LDSM2(b0, b1, hB + (uint32_t)(ks >> 2) * SLAB + (uint32_t)(ks & 3) * 32);
                MMA16816(ec[q], Af[ks][0], Af[ks][1], Af[ks][2], Af[ks][3], b0, b1);
            }
            if (t > 0) {
                if (p) { MBAR_WAIT(mbB, (uint32_t)phB1); phB1 ^= 1; }
                else   { MBAR_WAIT(mbB, (uint32_t)phB0); phB0 ^= 1; }
            }
            if (tid == 0)
                asm volatile("mbarrier.arrive.expect_tx.shared.b64 _, [%0], %1;"
                             :: "r"(mbB), "r"(TXH) : "memory");
            int q = 0;
#pragma unroll
            for (int ks = 0; ks < 16; ks++) {
                if (ks >= ksOwn && ks < ksOwn + 4) continue;
                uint32_t b0, b1;
                LDSM2(b0, b1, hB + (uint32_t)(ks >> 2) * SLAB + (uint32_t)(ks & 3) * 32);
                MMA16816(ec[q & 3], Af[ks][0], Af[ks][1], Af[ks][2], Af[ks][3], b0, b1);
                q++;
            }
        }
        float dHi[4];
#pragma unroll
        for (int e = 0; e < 4; e++)
            dHi[e] = (ec[0][e] + ec[1][e]) + (ec[2][e] + ec[3][e]);

        float xc = __shfl_xor_sync(0xFFFFFFFFu, lo16 ? dHi[1] : dHi[0], 16);
        float xd = __shfl_xor_sync(0xFFFFFFFFu, lo16 ? dHi[3] : dHi[2], 16);
        float zB0, zB1, zB2, zB3;
        if (lo16) { zB0 = dHi[0]; zB1 = xc;     zB2 = dHi[2]; zB3 = xd;     }
        else      { zB0 = xc;     zB1 = dHi[1]; zB2 = xd;     zB3 = dHi[3]; }

        float av1 = ftanh(zB0 + xwb.x);
        float iv1 = hsig (zB1 + xwb.y);
        float fv1 = hsig (zB2 + xwb.z);
        float ov1 = hsig (zB3 + xwb.w);
        c1 = fmaf(fv1, c1, av1 * iv1);
        float h1 = ov1 * ftanh(c1);

        float q1 = __shfl_xor_sync(0xFFFFFFFFu, h1, 4);
        if (sender) {
            __half2 v = __floats2half2_rn(h1, q1);
            const uint32_t off = (uint32_t)(cell0 + 8) * 144 + (uint32_t)uloc * 2;
            *(__half2*)(smem + OFF_STG + p * SLAB + off) = v;
            *(__half2*)(smem + OFF_H + (p ^ 1) * HBUF + rank * SLAB + off) = v;
        }

        __syncthreads();
        if (tid == 0) {
            asm volatile("fence.proxy.async;" ::: "memory");
            const uint32_t src  = sb + OFF_STG + (uint32_t)p * SLAB + HALFB;
            const uint32_t dstL = sb + OFF_H + (uint32_t)(p ^ 1) * HBUF + rank * SLAB + HALFB;
            const uint32_t mbL  = sb + OFF_MB + (uint32_t)(p ^ 1) * 16 + 8;
#pragma unroll
            for (int peer = 0; peer < 4; peer++) {
                if (peer == (int)rank) continue;
                uint32_t dstR, mbR;
                asm("mapa.shared::cluster.u32 %0, %1, %2;" : "=r"(dstR) : "r"(dstL), "r"(peer));
                asm("mapa.shared::cluster.u32 %0, %1, %2;" : "=r"(mbR)  : "r"(mbL),  "r"(peer));
                asm volatile(
                    "cp.async.bulk.shared::cluster.shared::cta.mbarrier::complete_tx::bytes "
                    "[%0], [%1], %2, [%3];"
                    :: "r"(dstR), "r"(src), "r"((uint32_t)HALFB), "r"(mbR) : "memory");
            }
        }
        out[(((size_t)(cell0 + 8) * T_ + t) * K_ + k) * UN_ + (size_t)rank * 64 + uloc] = h1;
    }

    asm volatile("barrier.cluster.arrive.aligned;" ::: "memory");
    asm volatile("barrier.cluster.wait.aligned;" ::: "memory");
}

// ---------------------------------------------------------------------------
// Launch: fork GEMM and recurrence onto independent graph branches (overlap).
// ---------------------------------------------------------------------------
extern "C" void kernel_launch(void* const* d_in, const int* in_sizes, int n_in,
                              void* d_out, int out_size)
{
    const float* x = (const float*)d_in[0];
    const float* W = (const float*)d_in[1];
    const float* U = (const float*)d_in[2];
    const float* b = (const float*)d_in[3];
    float* out = (float*)d_out;

    static cudaStream_t s2 = nullptr;
    static cudaEvent_t evFork = nullptr, evJoin = nullptr;
    static void* flagsPtr = nullptr;
    if (!s2) {
        cudaStreamCreateWithFlags(&s2, cudaStreamNonBlocking);
        cudaEventCreateWithFlags(&evFork, cudaEventDisableTiming);
        cudaEventCreateWithFlags(&evJoin, cudaEventDisableTiming);
        cudaGetSymbolAddress(&flagsPtr, g_flags);
        cudaFuncSetAttribute(gemm_xw_hmma, cudaFuncAttributeMaxDynamicSharedMemorySize, SM1_TOT);
        cudaFuncSetAttribute(lstm_rec_v7, cudaFuncAttributeMaxDynamicSharedMemorySize, SM2_TOT);
    }

    cudaMemsetAsync(flagsPtr, 0, sizeof(unsigned int) * K_ * 8, 0);

    cudaEventRecord(evFork, 0);
    cudaStreamWaitEvent(s2, evFork, 0);

    lstm_rec_v7<<<K_ * 4, 512, SM2_TOT, s2>>>(U, out);

    dim3 g1(8, 128, 8);
    gemm_xw_hmma<<<g1, 256, SM1_TOT, 0>>>(x, W, b);

    cudaEventRecord(evJoin, s2);
    cudaStreamWaitEvent(0, evJoin, 0);
}

// round 15
// speedup vs baseline: 3.0691x; 3.0691x over previous
#include <cuda_runtime.h>
#include <cuda_fp16.h>
#include <cstdint>

#define B_  16
#define T_  512
#define K_  8
#define NI_ 256
#define UN_ 256
#define G_  1024   // 4*UNITS

// Hoisted x@W + b, GATE-INTERLEAVED: col = 4*u + g  (u=unit 0..255, g=gate).
__device__ float g_xw[(size_t)B_ * T_ * K_ * G_];
// Progress flags: g_flags[k][chunk] counts completed GEMM blocks (target 128).
__device__ unsigned int g_flags[K_][8];

__device__ __forceinline__ uint32_t smem_u32(const void* p) {
    uint32_t a;
    asm("{ .reg .u64 t; cvta.to.shared.u64 t, %1; cvt.u32.u64 %0, t; }" : "=r"(a) : "l"(p));
    return a;
}
__device__ __forceinline__ float hsig(float v) {
    return fminf(fmaxf(fmaf(v, 0.2f, 0.5f), 0.0f), 1.0f);
}
// Branchless tanh: (e^2x - 1)/(e^2x + 1), clamped. On the h->h critical chain.
__device__ __forceinline__ float ftanh(float x) {
    float xc = fminf(fmaxf(x, -9.0f), 9.0f);
    float e = __expf(2.0f * xc);
    return __fdividef(e - 1.0f, e + 1.0f);
}

#define LDSM4(r0, r1, r2, r3, addr)                                              \
    asm volatile("ldmatrix.sync.aligned.m8n8.x4.shared.b16 {%0,%1,%2,%3}, [%4];" \
                 : "=r"(r0), "=r"(r1), "=r"(r2), "=r"(r3) : "r"(addr))
#define LDSM2(r0, r1, addr)                                                      \
    asm volatile("ldmatrix.sync.aligned.m8n8.x2.shared.b16 {%0,%1}, [%2];"       \
                 : "=r"(r0), "=r"(r1) : "r"(addr))
#define LDSM4T(r0, r1, r2, r3, addr)                                             \
    asm volatile("ldmatrix.sync.aligned.m8n8.x4.trans.shared.b16 {%0,%1,%2,%3}, [%4];" \
                 : "=r"(r0), "=r"(r1), "=r"(r2), "=r"(r3) : "r"(addr))
#define MMA16816(d, a0, a1, a2, a3, b0, b1)                                      \
    asm volatile("mma.sync.aligned.m16n8k16.row.col.f32.f16.f16.f32 "            \
                 "{%0,%1,%2,%3}, {%4,%5,%6,%7}, {%8,%9}, {%0,%1,%2,%3};"         \
                 : "+f"(d[0]), "+f"(d[1]), "+f"(d[2]), "+f"(d[3])                \
                 : "r"(a0), "r"(a1), "r"(a2), "r"(a3), "r"(b0), "r"(b1))

#define MBAR_WAIT(addr, ph) do {                                                          \
    uint32_t _done;                                                                       \
    asm volatile("{ .reg .pred p; mbarrier.try_wait.parity.acquire.cta.shared::cta.b64 "  \
                 "p, [%1], %2; selp.b32 %0,1,0,p; }"                                      \
                 : "=r"(_done) : "r"(addr), "r"(ph) : "memory");                          \
    while (!_done) {                                                                      \
        asm volatile("{ .reg .pred p; mbarrier.try_wait.parity.acquire.cta.shared::cta.b64 " \
                     "p, [%1], %2, 0x989680; selp.b32 %0,1,0,p; }"                        \
                     : "=r"(_done) : "r"(addr), "r"(ph) : "memory");                      \
    }                                                                                     \
} while (0)

// ---------------------------------------------------------------------------
// Kernel 1 (HMMA): x@W + b into g_xw, col = 4u+g. M-tile 64 (2 blocks/SM),
// 8 chunk-major t-chunks of 64 steps, release completion flags. (R13-proven.)
// ---------------------------------------------------------------------------
#define AP 264
#define BP 136
#define SM1_A 0
#define SM1_B (64 * AP * 2)
#define SM1_TOT (SM1_B + 256 * BP * 2)

__global__ __launch_bounds__(256, 2) void gemm_xw_hmma(
    const float* __restrict__ x, const float* __restrict__ W,
    const float* __restrict__ bias)
{
    extern __shared__ char smem[];
    const uint32_t sb = smem_u32(smem);
    const int tid = threadIdx.x, w = tid >> 5, l = tid & 31;
    const int nb    = blockIdx.x;
    const int k     = blockIdx.y >> 4;
    const int cell  = blockIdx.y & 15;
    const int chunk = blockIdx.z;
    const int bm    = (cell * 8 + chunk) * 64;

    half* As = (half*)(smem + SM1_A);
    for (int idx = tid; idx < 64 * 64; idx += 256) {
        int r = idx >> 6, c4 = idx & 63;
        float4 v = *(const float4*)(x + ((size_t)(bm + r) * K_ + k) * NI_ + c4 * 4);
        __half2 h01 = __floats2half2_rn(v.x, v.y);
        __half2 h23 = __floats2half2_rn(v.z, v.w);
        uint2 pk = make_uint2(*(uint32_t*)&h01, *(uint32_t*)&h23);
        *(uint2*)(As + r * AP + c4 * 4) = pk;
    }
    half* Bs = (half*)(smem + SM1_B);
    for (int idx = tid; idx < 256 * 128; idx += 256) {
        int i = idx >> 7, np = idx & 127;
        int u = np >> 2, g = np & 3;
        Bs[i * BP + np] = __float2half_rn(
            W[((size_t)k * NI_ + i) * G_ + g * 256 + nb * 32 + u]);
    }
    __syncthreads();

    const int wm = w >> 2, wn = w & 3;
    float acc[2][4][4];
#pragma unroll
    for (int a = 0; a < 2; a++)
#pragma unroll
        for (int b = 0; b < 4; b++)
#pragma unroll
            for (int e = 0; e < 4; e++) acc[a][b][e] = 0.0f;

#pragma unroll
    for (int ks = 0; ks < 16; ks++) {
        uint32_t af[2][4], bf[2][4];
#pragma unroll
        for (int ma = 0; ma < 2; ma++) {
            uint32_t aaddr = sb + SM1_A
                + (uint32_t)(wm * 32 + ma * 16 + (l & 15)) * (AP * 2)
                + (uint32_t)ks * 32 + (uint32_t)(l >> 4) * 16;
            LDSM4(af[ma][0], af[ma][1], af[ma][2], af[ma][3], aaddr);
        }
#pragma unroll
        for (int n2 = 0; n2 < 2; n2++) {
            uint32_t baddr = sb + SM1_B
                + (uint32_t)(ks * 16 + ((l >> 3) & 1) * 8 + (l & 7)) * (BP * 2)
                + (uint32_t)(wn * 32 + n2 * 16 + (l >> 4) * 8) * 2;
            LDSM4T(bf[n2][0], bf[n2][1], bf[n2][2], bf[n2][3], baddr);
        }
#pragma unroll
        for (int ma = 0; ma < 2; ma++) {
            MMA16816(acc[ma][0], af[ma][0], af[ma][1], af[ma][2], af[ma][3], bf[0][0], bf[0][1]);
            MMA16816(acc[ma][1], af[ma][0], af[ma][1], af[ma][2], af[ma][3], bf[0][2], bf[0][3]);
            MMA16816(acc[ma][2], af[ma][0], af[ma][1], af[ma][2], af[ma][3], bf[1][0], bf[1][1]);
            MMA16816(acc[ma][3], af[ma][0], af[ma][1], af[ma][2], af[ma][3], bf[1][2], bf[1][3]);
        }
    }

#pragma unroll
    for (int nt = 0; nt < 4; nt++) {
        const int np = wn * 32 + nt * 8 + (l & 3) * 2;
        const int u = np >> 2, g = np & 3;
        const float b0 = __ldg(bias + (size_t)k * G_ + g * 256 + nb * 32 + u);
        const float b1 = __ldg(bias + (size_t)k * G_ + (g + 1) * 256 + nb * 32 + u);
#pragma unroll
        for (int ma = 0; ma < 2; ma++) {
            const int m0 = bm + wm * 32 + ma * 16 + (l >> 2);
            float* p0 = g_xw + ((size_t)m0 * K_ + k) * G_ + nb * 128 + np;
            float* p1 = g_xw + ((size_t)(m0 + 8) * K_ + k) * G_ + nb * 128 + np;
            *(float2*)p0 = make_float2(acc[ma][nt][0] + b0, acc[ma][nt][1] + b1);
            *(float2*)p1 = make_float2(acc[ma][nt][2] + b0, acc[ma][nt][3] + b1);
        }
    }

    __threadfence();
    __syncthreads();
    if (tid == 0)
        asm volatile("red.release.gpu.global.add.u32 [%0], %1;"
                     :: "l"(&g_flags[k][chunk]), "r"(1u) : "memory");
}

// ---------------------------------------------------------------------------
// Kernel 2: recurrence v8 = R13's v6 + storage-rotated local-first MMA.
// Af[q] holds the U fragment for ks2(q) = 4*((rank + q/4)&3) + (q&3), loaded
// once at init, so group j = q>>2 is COMPILE-TIME: group 0 is the local slab
// (issued before the mbarrier wait), groups 1-3 are remote (after). All
// register-array indices are compile-time (R14's runtime-indexed arrays
// spilled to local memory -> 3.3x regression).
// ---------------------------------------------------------------------------
#define UTP   264
#define SLAB  2304
#define HALFB 1152
#define HBUF  (4 * SLAB)
#define TXH   (3u * HALFB)
#define OFF_H   0
#define OFF_STG (2 * HBUF)
#define OFF_MB  (OFF_STG + 2 * SLAB)
#define OFF_UT  (OFF_MB + 128)
#define SM2_TOT (OFF_UT + 256 * UTP * 2)

__global__ __launch_bounds__(512, 1) __cluster_dims__(4, 1, 1)
void lstm_rec_v8(const float* __restrict__ U, float* __restrict__ out)
{
    extern __shared__ char smem[];
    const uint32_t sb = smem_u32(smem);
    const int tid = threadIdx.x, w = tid >> 5, l = tid & 31;
    const int k = blockIdx.x >> 2;
    uint32_t rank;
    asm("mov.u32 %0, %%cluster_ctarank;" : "=r"(rank));

    {
        const int j = tid >> 1, hf = tid & 1;
        const int wq = j >> 4, rr = j & 15;
        const int uloc = 4 * wq + (rr & 3), g = rr >> 2;
        const float* up = U + (size_t)k * NI_ * G_ + g * 256 + (int)rank * 64 + uloc;
        half* uts = (half*)(smem + OFF_UT) + (size_t)j * UTP;
        for (int i = hf * 128; i < hf * 128 + 128; i++)
            uts[i] = __float2half_rn(up[(size_t)i * G_]);
    }
    for (int idx = tid; idx < HBUF / 4; idx += 512)
        ((uint32_t*)(smem + OFF_H))[idx] = 0u;
    if (tid == 0) {
#pragma unroll
        for (int b = 0; b < 4; b++)
            asm volatile("mbarrier.init.shared.b64 [%0], %1;"
                         :: "r"(sb + OFF_MB + b * 8), "r"(1u) : "memory");
        asm volatile("mbarrier.arrive.expect_tx.shared.b64 _, [%0], %1;"
                     :: "r"(sb + OFF_MB + 16), "r"(TXH) : "memory");
        asm volatile("mbarrier.arrive.expect_tx.shared.b64 _, [%0], %1;"
                     :: "r"(sb + OFF_MB + 24), "r"(TXH) : "memory");
    }
    __syncthreads();

    // UT -> A-frags, ROTATED: Af[q] = fragment for ks2 = 4*((rank+q/4)&3)+(q&3).
    uint32_t Af[16][4];
    {
        const uint32_t abase = sb + OFF_UT
            + (uint32_t)(16 * w + (l & 15)) * (UTP * 2) + (uint32_t)(l >> 4) * 16;
#pragma unroll
        for (int q = 0; q < 16; q++) {
            const int ks2 = 4 * (((int)rank + (q >> 2)) & 3) + (q & 3);
            LDSM4(Af[q][0], Af[q][1], Af[q][2], Af[q][3], abase + (uint32_t)ks2 * 32);
        }
    }

    asm volatile("barrier.cluster.arrive.aligned;" ::: "memory");
    asm volatile("barrier.cluster.wait.aligned;" ::: "memory");

    const bool lo16 = (l < 16);
    const int  uloc = 4 * w + ((l >> 2) & 3);
    const int  cell0 = 2 * (l & 3) + (lo16 ? 0 : 1);
    const int  colx = 4 * ((int)rank * 64 + uloc);
    const uint32_t aHalf = sb + OFF_H + (uint32_t)(l & 7) * 144 + (uint32_t)((l >> 3) & 1) * 16;
    // Rotated slab bases: slabA[j] = slab holding units of CTA (rank+j)&3.
    uint32_t slabA[4];
#pragma unroll
    for (int j = 0; j < 4; j++)
        slabA[j] = aHalf + (uint32_t)(((int)rank + j) & 3) * SLAB;
    const float* xw0p = g_xw + ((size_t)cell0 * T_ * K_ + k) * G_ + colx;
    const float* xw1p = g_xw + ((size_t)(cell0 + 8) * T_ * K_ + k) * G_ + colx;
    const bool sender = ((l >> 2) & 1) == 0;
    float c0 = 0.0f, c1 = 0.0f;
    int phA0 = 0, phA1 = 0, phB0 = 0, phB1 = 0;

    for (int t = 0; t < T_; t++) {
        const int p = t & 1;
        const uint32_t mbA = sb + OFF_MB + (uint32_t)p * 16;
        const uint32_t mbB = mbA + 8;
        const uint32_t hOff = (uint32_t)p * HBUF;

        if ((t & 63) == 0) {
            const int ch = t >> 6;
            unsigned int v;
            do {
                asm volatile("ld.acquire.gpu.global.u32 %0, [%1];"
                             : "=r"(v) : "l"(&g_flags[k][ch]) : "memory");
                if (v < 64u) __nanosleep(1000);
            } while (v < 128u);
        }

        float4 xwa = __ldcg((const float4*)(xw0p + (size_t)t * (K_ * G_)));
        float4 xwb = __ldcg((const float4*)(xw1p + (size_t)t * (K_ * G_)));

        // ================= PHASE A : cells 0-7 =================
        float dP[4] = {0, 0, 0, 0}, dQ[4] = {0, 0, 0, 0};
        // Group 0 = LOCAL slab (written by this CTA; visible since previous
        // phase's __syncthreads; no remote ever writes it): issue pre-wait.
#pragma unroll
        for (int qq = 0; qq < 4; qq++) {
            uint32_t b0, b1;
            LDSM2(b0, b1, slabA[0] + hOff + (uint32_t)qq * 32);
            MMA16816(dP, Af[qq][0], Af[qq][1], Af[qq][2], Af[qq][3], b0, b1);
        }
        if (t > 0) {
            if (p) { MBAR_WAIT(mbA, (uint32_t)phA1); phA1 ^= 1; }
            else   { MBAR_WAIT(mbA, (uint32_t)phA0); phA0 ^= 1; }
        }
        if (tid == 0)
            asm volatile("mbarrier.arrive.expect_tx.shared.b64 _, [%0], %1;"
                         :: "r"(mbA), "r"(TXH) : "memory");
        // Groups 1-3 (remote slabs), compile-time indices throughout.
#pragma unroll
        for (int j = 1; j < 4; j++) {
#pragma unroll
            for (int qq = 0; qq < 4; qq++) {
                const int q = 4 * j + qq;
                uint32_t b0, b1;
                LDSM2(b0, b1, slabA[j] + hOff + (uint32_t)qq * 32);
                if (j & 1) { MMA16816(dQ, Af[q][0], Af[q][1], Af[q][2], Af[q][3], b0, b1); }
                else       { MMA16816(dP, Af[q][0], Af[q][1], Af[q][2], Af[q][3], b0, b1); }
            }
        }
        float dLo[4];
#pragma unroll
        for (int e = 0; e < 4; e++) dLo[e] = dP[e] + dQ[e];

        float xa = __shfl_xor_sync(0xFFFFFFFFu, lo16 ? dLo[1] : dLo[0], 16);
        float xb = __shfl_xor_sync(0xFFFFFFFFu, lo16 ? dLo[3] : dLo[2], 16);
        float zA0, zA1, zA2, zA3;
        if (lo16) { zA0 = dLo[0]; zA1 = xa;     zA2 = dLo[2]; zA3 = xb;     }
        else      { zA0 = xa;     zA1 = dLo[1]; zA2 = xb;     zA3 = dLo[3]; }

        float av0 = ftanh(zA0 + xwa.x);
        float iv0 = hsig (zA1 + xwa.y);
        float fv0 = hsig (zA2 + xwa.z);
        float ov0 = hsig (zA3 + xwa.w);
        c0 = fmaf(fv0, c0, av0 * iv0);
        float h0 = ov0 * ftanh(c0);

        float q0 = __shfl_xor_sync(0xFFFFFFFFu, h0, 4);
        if (sender) {
            __half2 v = __floats2half2_rn(h0, q0);
            const uint32_t off = (uint32_t)cell0 * 144 + (uint32_t)uloc * 2;
            *(__half2*)(smem + OFF_STG + p * SLAB + off) = v;
            *(__half2*)(smem + OFF_H + (p ^ 1) * HBUF + rank * SLAB + off) = v;
        }

        __syncthreads();
        if (tid == 0) {
            asm volatile("fence.proxy.async;" ::: "memory");
            const uint32_t src  = sb + OFF_STG + (uint32_t)p * SLAB;
            const uint32_t dstL = sb + OFF_H + (uint32_t)(p ^ 1) * HBUF + rank * SLAB;
            const uint32_t mbL  = sb + OFF_MB + (uint32_t)(p ^ 1) * 16;
#pragma unroll
            for (int peer = 0; peer < 4; peer++) {
                if (peer == (int)rank) continue;
                uint32_t dstR, mbR;
                asm("mapa.shared::cluster.u32 %0, %1, %2;" : "=r"(dstR) : "r"(dstL), "r"(peer));
                asm("mapa.shared::cluster.u32 %0, %1, %2;" : "=r"(mbR)  : "r"(mbL),  "r"(peer));
                asm volatile(
                    "cp.async.bulk.shared::cluster.shared::cta.mbarrier::complete_tx::bytes "
                    "[%0], [%1], %2, [%3];"
                    :: "r"(dstR), "r"(src), "r"((uint32_t)HALFB), "r"(mbR) : "memory");
            }
        }
        out[(((size_t)cell0 * T_ + t) * K_ + k) * UN_ + (size_t)rank * 64 + uloc] = h0;

        // ================= PHASE B : cells 8-15 =================
        float eP[4] = {0, 0, 0, 0}, eQ[4] = {0, 0, 0, 0};
#pragma unroll
        for (int qq = 0; qq < 4; qq++) {
            uint32_t b0, b1;
            LDSM2(b0, b1, slabA[0] + hOff + 1152u + (uint32_t)qq * 32);
            MMA16816(eP, Af[qq][0], Af[qq][1], Af[qq][2], Af[qq][3], b0, b1);
        }
        if (t > 0) {
            if (p) { MBAR_WAIT(mbB, (uint32_t)phB1); phB1 ^= 1; }
            else   { MBAR_WAIT(mbB, (uint32_t)phB0); phB0 ^= 1; }
        }
        if (tid == 0)
            asm volatile("mbarrier.arrive.expect_tx.shared.b64 _, [%0], %1;"
                         :: "r"(mbB), "r"(TXH) : "memory");
#pragma unroll
        for (int j = 1; j < 4; j++) {
#pragma unroll
            for (int qq = 0; qq < 4; qq++) {
                const int q = 4 * j + qq;
                uint32_t b0, b1;
                LDSM2(b0, b1, slabA[j] + hOff + 1152u + (uint32_t)qq * 32);
                if (j & 1) { MMA16816(eQ, Af[q][0], Af[q][1], Af[q][2], Af[q][3], b0, b1); }
                else       { MMA16816(eP, Af[q][0], Af[q][1], Af[q][2], Af[q][3], b0, b1); }
            }
        }
        float dHi[4];
#pragma unroll
        for (int e = 0; e < 4; e++) dHi[e] = eP[e] + eQ[e];

        float xc = __shfl_xor_sync(0xFFFFFFFFu, lo16 ? dHi[1] : dHi[0], 16);
        float xd = __shfl_xor_sync(0xFFFFFFFFu, lo16 ? dHi[3] : dHi[2], 16);
        float zB0, zB1, zB2, zB3;
        if (lo16) { zB0 = dHi[0]; zB1 = xc;     zB2 = dHi[2]; zB3 = xd;     }
        else      { zB0 = xc;     zB1 = dHi[1]; zB2 = xd;     zB3 = dHi[3]; }

        float av1 = ftanh(zB0 + xwb.x);
        float iv1 = hsig (zB1 + xwb.y);
        float fv1 = hsig (zB2 + xwb.z);
        float ov1 = hsig (zB3 + xwb.w);
        c1 = fmaf(fv1, c1, av1 * iv1);
        float h1 = ov1 * ftanh(c1);

        float q1 = __shfl_xor_sync(0xFFFFFFFFu, h1, 4);
        if (sender) {
            __half2 v = __floats2half2_rn(h1, q1);
            const uint32_t off = (uint32_t)(cell0 + 8) * 144 + (uint32_t)uloc * 2;
            *(__half2*)(smem + OFF_STG + p * SLAB + off) = v;
            *(__half2*)(smem + OFF_H + (p ^ 1) * HBUF + rank * SLAB + off) = v;
        }

        __syncthreads();
        if (tid == 0) {
            asm volatile("fence.proxy.async;" ::: "memory");
            const uint32_t src  = sb + OFF_STG + (uint32_t)p * SLAB + HALFB;
            const uint32_t dstL = sb + OFF_H + (uint32_t)(p ^ 1) * HBUF + rank * SLAB + HALFB;
            const uint32_t mbL  = sb + OFF_MB + (uint32_t)(p ^ 1) * 16 + 8;
#pragma unroll
            for (int peer = 0; peer < 4; peer++) {
                if (peer == (int)rank) continue;
                uint32_t dstR, mbR;
                asm("mapa.shared::cluster.u32 %0, %1, %2;" : "=r"(dstR) : "r"(dstL), "r"(peer));
                asm("mapa.shared::cluster.u32 %0, %1, %2;" : "=r"(mbR)  : "r"(mbL),  "r"(peer));
                asm volatile(
                    "cp.async.bulk.shared::cluster.shared::cta.mbarrier::complete_tx::bytes "
                    "[%0], [%1], %2, [%3];"
                    :: "r"(dstR), "r"(src), "r"((uint32_t)HALFB), "r"(mbR) : "memory");
            }
        }
        out[(((size_t)(cell0 + 8) * T_ + t) * K_ + k) * UN_ + (size_t)rank * 64 + uloc] = h1;
    }

    asm volatile("barrier.cluster.arrive.aligned;" ::: "memory");
    asm volatile("barrier.cluster.wait.aligned;" ::: "memory");
}

// ---------------------------------------------------------------------------
// Launch: fork GEMM and recurrence onto independent graph branches (overlap).
// ---------------------------------------------------------------------------
extern "C" void kernel_launch(void* const* d_in, const int* in_sizes, int n_in,
                              void* d_out, int out_size)
{
    const float* x = (const float*)d_in[0];
    const float* W = (const float*)d_in[1];
    const float* U = (const float*)d_in[2];
    const float* b = (const float*)d_in[3];
    float* out = (float*)d_out;

    static cudaStream_t s2 = nullptr;
    static cudaEvent_t evFork = nullptr, evJoin = nullptr;
    static void* flagsPtr = nullptr;
    if (!s2) {
        cudaStreamCreateWithFlags(&s2, cudaStreamNonBlocking);
        cudaEventCreateWithFlags(&evFork, cudaEventDisableTiming);
        cudaEventCreateWithFlags(&evJoin, cudaEventDisableTiming);
        cudaGetSymbolAddress(&flagsPtr, g_flags);
        cudaFuncSetAttribute(gemm_xw_hmma, cudaFuncAttributeMaxDynamicSharedMemorySize, SM1_TOT);
        cudaFuncSetAttribute(lstm_rec_v8, cudaFuncAttributeMaxDynamicSharedMemorySize, SM2_TOT);
    }

    cudaMemsetAsync(flagsPtr, 0, sizeof(unsigned int) * K_ * 8, 0);

    cudaEventRecord(evFork, 0);
    cudaStreamWaitEvent(s2, evFork, 0);

    lstm_rec_v8<<<K_ * 4, 512, SM2_TOT, s2>>>(U, out);

    dim3 g1(8, 128, 8);
    gemm_xw_hmma<<<g1, 256, SM1_TOT, 0>>>(x, W, b);

    cudaEventRecord(evJoin, s2);
    cudaStreamWaitEvent(0, evJoin, 0);
}

// round 16
// speedup vs baseline: 3.2509x; 1.0593x over previous
#include <cuda_runtime.h>
#include <cuda_fp16.h>
#include <cstdint>

#define B_  16
#define T_  512
#define K_  8
#define NI_ 256
#define UN_ 256
#define G_  1024   // 4*UNITS

// Hoisted x@W + b, GATE-INTERLEAVED: col = 4*u + g  (u=unit 0..255, g=gate).
__device__ float g_xw[(size_t)B_ * T_ * K_ * G_];
// Progress flags: g_flags[k][chunk] counts completed GEMM blocks (target 128).
__device__ unsigned int g_flags[K_][8];

__device__ __forceinline__ uint32_t smem_u32(const void* p) {
    uint32_t a;
    asm("{ .reg .u64 t; cvta.to.shared.u64 t, %1; cvt.u32.u64 %0, t; }" : "=r"(a) : "l"(p));
    return a;
}
__device__ __forceinline__ float hsig(float v) {
    return fminf(fmaxf(fmaf(v, 0.2f, 0.5f), 0.0f), 1.0f);
}
// Branchless tanh: (e^2x - 1)/(e^2x + 1), clamped. On the h->h critical chain.
__device__ __forceinline__ float ftanh(float x) {
    float xc = fminf(fmaxf(x, -9.0f), 9.0f);
    float e = __expf(2.0f * xc);
    return __fdividef(e - 1.0f, e + 1.0f);
}

#define LDSM4(r0, r1, r2, r3, addr)                                              \
    asm volatile("ldmatrix.sync.aligned.m8n8.x4.shared.b16 {%0,%1,%2,%3}, [%4];" \
                 : "=r"(r0), "=r"(r1), "=r"(r2), "=r"(r3) : "r"(addr))
#define LDSM2(r0, r1, addr)                                                      \
    asm volatile("ldmatrix.sync.aligned.m8n8.x2.shared.b16 {%0,%1}, [%2];"       \
                 : "=r"(r0), "=r"(r1) : "r"(addr))
#define LDSM4T(r0, r1, r2, r3, addr)                                             \
    asm volatile("ldmatrix.sync.aligned.m8n8.x4.trans.shared.b16 {%0,%1,%2,%3}, [%4];" \
                 : "=r"(r0), "=r"(r1), "=r"(r2), "=r"(r3) : "r"(addr))
#define MMA16816(d, a0, a1, a2, a3, b0, b1)                                      \
    asm volatile("mma.sync.aligned.m16n8k16.row.col.f32.f16.f16.f32 "            \
                 "{%0,%1,%2,%3}, {%4,%5,%6,%7}, {%8,%9}, {%0,%1,%2,%3};"         \
                 : "+f"(d[0]), "+f"(d[1]), "+f"(d[2]), "+f"(d[3])                \
                 : "r"(a0), "r"(a1), "r"(a2), "r"(a3), "r"(b0), "r"(b1))

#define MBAR_WAIT(addr, ph) do {                                                          \
    uint32_t _done;                                                                       \
    asm volatile("{ .reg .pred p; mbarrier.try_wait.parity.acquire.cta.shared::cta.b64 "  \
                 "p, [%1], %2; selp.b32 %0,1,0,p; }"                                      \
                 : "=r"(_done) : "r"(addr), "r"(ph) : "memory");                          \
    while (!_done) {                                                                      \
        asm volatile("{ .reg .pred p; mbarrier.try_wait.parity.acquire.cta.shared::cta.b64 " \
                     "p, [%1], %2, 0x989680; selp.b32 %0,1,0,p; }"                        \
                     : "=r"(_done) : "r"(addr), "r"(ph) : "memory");                      \
    }                                                                                     \
} while (0)

// ---------------------------------------------------------------------------
// Kernel 1 (HMMA): x@W + b into g_xw, col = 4u+g. M-tile 64 (2 blocks/SM),
// 8 chunk-major t-chunks of 64 steps, release completion flags. (R13-proven.)
// ---------------------------------------------------------------------------
#define AP 264
#define BP 136
#define SM1_A 0
#define SM1_B (64 * AP * 2)
#define SM1_TOT (SM1_B + 256 * BP * 2)

__global__ __launch_bounds__(256, 2) void gemm_xw_hmma(
    const float* __restrict__ x, const float* __restrict__ W,
    const float* __restrict__ bias)
{
    extern __shared__ char smem[];
    const uint32_t sb = smem_u32(smem);
    const int tid = threadIdx.x, w = tid >> 5, l = tid & 31;
    const int nb    = blockIdx.x;
    const int k     = blockIdx.y >> 4;
    const int cell  = blockIdx.y & 15;
    const int chunk = blockIdx.z;
    const int bm    = (cell * 8 + chunk) * 64;

    half* As = (half*)(smem + SM1_A);
    for (int idx = tid; idx < 64 * 64; idx += 256) {
        int r = idx >> 6, c4 = idx & 63;
        float4 v = *(const float4*)(x + ((size_t)(bm + r) * K_ + k) * NI_ + c4 * 4);
        __half2 h01 = __floats2half2_rn(v.x, v.y);
        __half2 h23 = __floats2half2_rn(v.z, v.w);
        uint2 pk = make_uint2(*(uint32_t*)&h01, *(uint32_t*)&h23);
        *(uint2*)(As + r * AP + c4 * 4) = pk;
    }
    half* Bs = (half*)(smem + SM1_B);
    for (int idx = tid; idx < 256 * 128; idx += 256) {
        int i = idx >> 7, np = idx & 127;
        int u = np >> 2, g = np & 3;
        Bs[i * BP + np] = __float2half_rn(
            W[((size_t)k * NI_ + i) * G_ + g * 256 + nb * 32 + u]);
    }
    __syncthreads();

    const int wm = w >> 2, wn = w & 3;
    float acc[2][4][4];
#pragma unroll
    for (int a = 0; a < 2; a++)
#pragma unroll
        for (int b = 0; b < 4; b++)
#pragma unroll
            for (int e = 0; e < 4; e++) acc[a][b][e] = 0.0f;

#pragma unroll
    for (int ks = 0; ks < 16; ks++) {
        uint32_t af[2][4], bf[2][4];
#pragma unroll
        for (int ma = 0; ma < 2; ma++) {
            uint32_t aaddr = sb + SM1_A
                + (uint32_t)(wm * 32 + ma * 16 + (l & 15)) * (AP * 2)
                + (uint32_t)ks * 32 + (uint32_t)(l >> 4) * 16;
            LDSM4(af[ma][0], af[ma][1], af[ma][2], af[ma][3], aaddr);
        }
#pragma unroll
        for (int n2 = 0; n2 < 2; n2++) {
            uint32_t baddr = sb + SM1_B
                + (uint32_t)(ks * 16 + ((l >> 3) & 1) * 8 + (l & 7)) * (BP * 2)
                + (uint32_t)(wn * 32 + n2 * 16 + (l >> 4) * 8) * 2;
            LDSM4T(bf[n2][0], bf[n2][1], bf[n2][2], bf[n2][3], baddr);
        }
#pragma unroll
        for (int ma = 0; ma < 2; ma++) {
            MMA16816(acc[ma][0], af[ma][0], af[ma][1], af[ma][2], af[ma][3], bf[0][0], bf[0][1]);
            MMA16816(acc[ma][1], af[ma][0], af[ma][1], af[ma][2], af[ma][3], bf[0][2], bf[0][3]);
            MMA16816(acc[ma][2], af[ma][0], af[ma][1], af[ma][2], af[ma][3], bf[1][0], bf[1][1]);
            MMA16816(acc[ma][3], af[ma][0], af[ma][1], af[ma][2], af[ma][3], bf[1][2], bf[1][3]);
        }
    }

#pragma unroll
    for (int nt = 0; nt < 4; nt++) {
        const int np = wn * 32 + nt * 8 + (l & 3) * 2;
        const int u = np >> 2, g = np & 3;
        const float b0 = __ldg(bias + (size_t)k * G_ + g * 256 + nb * 32 + u);
        const float b1 = __ldg(bias + (size_t)k * G_ + (g + 1) * 256 + nb * 32 + u);
#pragma unroll
        for (int ma = 0; ma < 2; ma++) {
            const int m0 = bm + wm * 32 + ma * 16 + (l >> 2);
            float* p0 = g_xw + ((size_t)m0 * K_ + k) * G_ + nb * 128 + np;
            float* p1 = g_xw + ((size_t)(m0 + 8) * K_ + k) * G_ + nb * 128 + np;
            *(float2*)p0 = make_float2(acc[ma][nt][0] + b0, acc[ma][nt][1] + b1);
            *(float2*)p1 = make_float2(acc[ma][nt][2] + b0, acc[ma][nt][3] + b1);
        }
    }

    __threadfence();
    __syncthreads();
    if (tid == 0)
        asm volatile("red.release.gpu.global.add.u32 [%0], %1;"
                     :: "l"(&g_flags[k][chunk]), "r"(1u) : "memory");
}

// ---------------------------------------------------------------------------
// Kernel 2: recurrence v6 (R13, best known) with ONE change: the 3 remote
// bulk copies per phase are issued by threads 0/1/2 in parallel (peer =
// (rank+1+tid)&3), not serially by tid0. Everything else byte-identical.
// ---------------------------------------------------------------------------
#define UTP   264
#define SLAB  2304
#define HALFB 1152
#define HBUF  (4 * SLAB)
#define TXH   (3u * HALFB)
#define OFF_H   0
#define OFF_STG (2 * HBUF)
#define OFF_MB  (OFF_STG + 2 * SLAB)
#define OFF_UT  (OFF_MB + 128)
#define SM2_TOT (OFF_UT + 256 * UTP * 2)

__global__ __launch_bounds__(512, 1) __cluster_dims__(4, 1, 1)
void lstm_rec_v9(const float* __restrict__ U, float* __restrict__ out)
{
    extern __shared__ char smem[];
    const uint32_t sb = smem_u32(smem);
    const int tid = threadIdx.x, w = tid >> 5, l = tid & 31;
    const int k = blockIdx.x >> 2;
    uint32_t rank;
    asm("mov.u32 %0, %%cluster_ctarank;" : "=r"(rank));

    {
        const int j = tid >> 1, hf = tid & 1;
        const int wq = j >> 4, rr = j & 15;
        const int uloc = 4 * wq + (rr & 3), g = rr >> 2;
        const float* up = U + (size_t)k * NI_ * G_ + g * 256 + (int)rank * 64 + uloc;
        half* uts = (half*)(smem + OFF_UT) + (size_t)j * UTP;
        for (int i = hf * 128; i < hf * 128 + 128; i++)
            uts[i] = __float2half_rn(up[(size_t)i * G_]);
    }
    for (int idx = tid; idx < HBUF / 4; idx += 512)
        ((uint32_t*)(smem + OFF_H))[idx] = 0u;
    if (tid == 0) {
#pragma unroll
        for (int b = 0; b < 4; b++)
            asm volatile("mbarrier.init.shared.b64 [%0], %1;"
                         :: "r"(sb + OFF_MB + b * 8), "r"(1u) : "memory");
        asm volatile("mbarrier.arrive.expect_tx.shared.b64 _, [%0], %1;"
                     :: "r"(sb + OFF_MB + 16), "r"(TXH) : "memory");
        asm volatile("mbarrier.arrive.expect_tx.shared.b64 _, [%0], %1;"
                     :: "r"(sb + OFF_MB + 24), "r"(TXH) : "memory");
    }
    __syncthreads();

    uint32_t Af[16][4];
    {
        const uint32_t abase = sb + OFF_UT
            + (uint32_t)(16 * w + (l & 15)) * (UTP * 2) + (uint32_t)(l >> 4) * 16;
#pragma unroll
        for (int ks = 0; ks < 16; ks++)
            LDSM4(Af[ks][0], Af[ks][1], Af[ks][2], Af[ks][3], abase + ks * 32);
    }

    asm volatile("barrier.cluster.arrive.aligned;" ::: "memory");
    asm volatile("barrier.cluster.wait.aligned;" ::: "memory");

    const bool lo16 = (l < 16);
    const int  uloc = 4 * w + ((l >> 2) & 3);
    const int  cell0 = 2 * (l & 3) + (lo16 ? 0 : 1);
    const int  colx = 4 * ((int)rank * 64 + uloc);
    const uint32_t aHalf = sb + OFF_H + (uint32_t)(l & 7) * 144 + (uint32_t)((l >> 3) & 1) * 16;
    const float* xw0p = g_xw + ((size_t)cell0 * T_ * K_ + k) * G_ + colx;
    const float* xw1p = g_xw + ((size_t)(cell0 + 8) * T_ * K_ + k) * G_ + colx;
    const bool sender = ((l >> 2) & 1) == 0;
    // Distributed bulk issue: threads 0..2 each own one peer.
    const bool isIssuer = (tid < 3);
    const int  myPeer   = ((int)rank + 1 + tid) & 3;
    float c0 = 0.0f, c1 = 0.0f;
    int phA0 = 0, phA1 = 0, phB0 = 0, phB1 = 0;

    for (int t = 0; t < T_; t++) {
        const int p = t & 1;
        const uint32_t mbA = sb + OFF_MB + (uint32_t)p * 16;
        const uint32_t mbB = mbA + 8;

        if ((t & 63) == 0) {
            const int ch = t >> 6;
            unsigned int v;
            do {
                asm volatile("ld.acquire.gpu.global.u32 %0, [%1];"
                             : "=r"(v) : "l"(&g_flags[k][ch]) : "memory");
                if (v < 128u) __nanosleep(1000);
            } while (v < 128u);
        }

        float4 xwa = __ldcg((const float4*)(xw0p + (size_t)t * (K_ * G_)));
        float4 xwb = __ldcg((const float4*)(xw1p + (size_t)t * (K_ * G_)));

        // ================= PHASE A : cells 0-7 =================
        if (t > 0) {
            if (p) { MBAR_WAIT(mbA, (uint32_t)phA1); phA1 ^= 1; }
            else   { MBAR_WAIT(mbA, (uint32_t)phA0); phA0 ^= 1; }
        }
        if (tid == 0)
            asm volatile("mbarrier.arrive.expect_tx.shared.b64 _, [%0], %1;"
                         :: "r"(mbA), "r"(TXH) : "memory");

        float dP[4] = {0, 0, 0, 0}, dQ[4] = {0, 0, 0, 0};
        {
            const uint32_t hA = aHalf + (uint32_t)p * HBUF;
#pragma unroll
            for (int ks = 0; ks < 8; ks++) {
                uint32_t b0, b1;
                LDSM2(b0, b1, hA + (uint32_t)(ks >> 2) * SLAB + (uint32_t)(ks & 3) * 32);
                MMA16816(dP, Af[ks][0], Af[ks][1], Af[ks][2], Af[ks][3], b0, b1);
            }
#pragma unroll
            for (int ks = 8; ks < 16; ks++) {
                uint32_t b0, b1;
                LDSM2(b0, b1, hA + (uint32_t)(ks >> 2) * SLAB + (uint32_t)(ks & 3) * 32);
                MMA16816(dQ, Af[ks][0], Af[ks][1], Af[ks][2], Af[ks][3], b0, b1);
            }
        }
        float dLo[4];
#pragma unroll
        for (int e = 0; e < 4; e++) dLo[e] = dP[e] + dQ[e];

        float xa = __shfl_xor_sync(0xFFFFFFFFu, lo16 ? dLo[1] : dLo[0], 16);
        float xb = __shfl_xor_sync(0xFFFFFFFFu, lo16 ? dLo[3] : dLo[2], 16);
        float zA0, zA1, zA2, zA3;
        if (lo16) { zA0 = dLo[0]; zA1 = xa;     zA2 = dLo[2]; zA3 = xb;     }
        else      { zA0 = xa;     zA1 = dLo[1]; zA2 = xb;     zA3 = dLo[3]; }

        float av0 = ftanh(zA0 + xwa.x);
        float iv0 = hsig (zA1 + xwa.y);
        float fv0 = hsig (zA2 + xwa.z);
        float ov0 = hsig (zA3 + xwa.w);
        c0 = fmaf(fv0, c0, av0 * iv0);
        float h0 = ov0 * ftanh(c0);

        float q0 = __shfl_xor_sync(0xFFFFFFFFu, h0, 4);
        if (sender) {
            __half2 v = __floats2half2_rn(h0, q0);
            const uint32_t off = (uint32_t)cell0 * 144 + (uint32_t)uloc * 2;
            *(__half2*)(smem + OFF_STG + p * SLAB + off) = v;
            *(__half2*)(smem + OFF_H + (p ^ 1) * HBUF + rank * SLAB + off) = v;
        }
        out[(((size_t)cell0 * T_ + t) * K_ + k) * UN_ + (size_t)rank * 64 + uloc] = h0;

        __syncthreads();
        if (isIssuer) {
            asm volatile("fence.proxy.async;" ::: "memory");
            const uint32_t src  = sb + OFF_STG + (uint32_t)p * SLAB;
            const uint32_t dstL = sb + OFF_H + (uint32_t)(p ^ 1) * HBUF + rank * SLAB;
            const uint32_t mbL  = sb + OFF_MB + (uint32_t)(p ^ 1) * 16;
            uint32_t dstR, mbR;
            asm("mapa.shared::cluster.u32 %0, %1, %2;" : "=r"(dstR) : "r"(dstL), "r"(myPeer));
            asm("mapa.shared::cluster.u32 %0, %1, %2;" : "=r"(mbR)  : "r"(mbL),  "r"(myPeer));
            asm volatile(
                "cp.async.bulk.shared::cluster.shared::cta.mbarrier::complete_tx::bytes "
                "[%0], [%1], %2, [%3];"
                :: "r"(dstR), "r"(src), "r"((uint32_t)HALFB), "r"(mbR) : "memory");
        }

        // ================= PHASE B : cells 8-15 =================
        if (t > 0) {
            if (p) { MBAR_WAIT(mbB, (uint32_t)phB1); phB1 ^= 1; }
            else   { MBAR_WAIT(mbB, (uint32_t)phB0); phB0 ^= 1; }
        }
        if (tid == 0)
            asm volatile("mbarrier.arrive.expect_tx.shared.b64 _, [%0], %1;"
                         :: "r"(mbB), "r"(TXH) : "memory");

        float eP[4] = {0, 0, 0, 0}, eQ[4] = {0, 0, 0, 0};
        {
            const uint32_t hB = aHalf + (uint32_t)p * HBUF + 8u * 144u;
#pragma unroll
            for (int ks = 0; ks < 8; ks++) {
                uint32_t b0, b1;
                LDSM2(b0, b1, hB + (uint32_t)(ks >> 2) * SLAB + (uint32_t)(ks & 3) * 32);
                MMA16816(eP, Af[ks][0], Af[ks][1], Af[ks][2], Af[ks][3], b0, b1);
            }
#pragma unroll
            for (int ks = 8; ks < 16; ks++) {
                uint32_t b0, b1;
                LDSM2(b0, b1, hB + (uint32_t)(ks >> 2) * SLAB + (uint32_t)(ks & 3) * 32);
                MMA16816(eQ, Af[ks][0], Af[ks][1], Af[ks][2], Af[ks][3], b0, b1);
            }
        }
        float dHi[4];
#pragma unroll
        for (int e = 0; e < 4; e++) dHi[e] = eP[e] + eQ[e];

        float xc = __shfl_xor_sync(0xFFFFFFFFu, lo16 ? dHi[1] : dHi[0], 16);
        float xd = __shfl_xor_sync(0xFFFFFFFFu, lo16 ? dHi[3] : dHi[2], 16);
        float zB0, zB1, zB2, zB3;
        if (lo16) { zB0 = dHi[0]; zB1 = xc;     zB2 = dHi[2]; zB3 = xd;     }
        else      { zB0 = xc;     zB1 = dHi[1]; zB2 = xd;     zB3 = dHi[3]; }

        float av1 = ftanh(zB0 + xwb.x);
        float iv1 = hsig (zB1 + xwb.y);
        float fv1 = hsig (zB2 + xwb.z);
        float ov1 = hsig (zB3 + xwb.w);
        c1 = fmaf(fv1, c1, av1 * iv1);
        float h1 = ov1 * ftanh(c1);

        float q1 = __shfl_xor_sync(0xFFFFFFFFu, h1, 4);
        if (sender) {
            __half2 v = __floats2half2_rn(h1, q1);
            const uint32_t off = (uint32_t)(cell0 + 8) * 144 + (uint32_t)uloc * 2;
            *(__half2*)(smem + OFF_STG + p * SLAB + off) = v;
            *(__half2*)(smem + OFF_H + (p ^ 1) * HBUF + rank * SLAB + off) = v;
        }
        out[(((size_t)(cell0 + 8) * T_ + t) * K_ + k) * UN_ + (size_t)rank * 64 + uloc] = h1;

        __syncthreads();
        if (isIssuer) {
            asm volatile("fence.proxy.async;" ::: "memory");
            const uint32_t src  = sb + OFF_STG + (uint32_t)p * SLAB + HALFB;
            const uint32_t dstL = sb + OFF_H + (uint32_t)(p ^ 1) * HBUF + rank * SLAB + HALFB;
            const uint32_t mbL  = sb + OFF_MB + (uint32_t)(p ^ 1) * 16 + 8;
            uint32_t dstR, mbR;
            asm("mapa.shared::cluster.u32 %0, %1, %2;" : "=r"(dstR) : "r"(dstL), "r"(myPeer));
            asm("mapa.shared::cluster.u32 %0, %1, %2;" : "=r"(mbR)  : "r"(mbL),  "r"(myPeer));
            asm volatile(
                "cp.async.bulk.shared::cluster.shared::cta.mbarrier::complete_tx::bytes "
                "[%0], [%1], %2, [%3];"
                :: "r"(dstR), "r"(src), "r"((uint32_t)HALFB), "r"(mbR) : "memory");
        }
    }

    asm volatile("barrier.cluster.arrive.aligned;" ::: "memory");
    asm volatile("barrier.cluster.wait.aligned;" ::: "memory");
}

// ---------------------------------------------------------------------------
// Launch: fork GEMM and recurrence onto independent graph branches (overlap).
// ---------------------------------------------------------------------------
extern "C" void kernel_launch(void* const* d_in, const int* in_sizes, int n_in,
                              void* d_out, int out_size)
{
    const float* x = (const float*)d_in[0];
    const float* W = (const float*)d_in[1];
    const float* U = (const float*)d_in[2];
    const float* b = (const float*)d_in[3];
    float* out = (float*)d_out;

    static cudaStream_t s2 = nullptr;
    static cudaEvent_t evFork = nullptr, evJoin = nullptr;
    static void* flagsPtr = nullptr;
    if (!s2) {
        cudaStreamCreateWithFlags(&s2, cudaStreamNonBlocking);
        cudaEventCreateWithFlags(&evFork, cudaEventDisableTiming);
        cudaEventCreateWithFlags(&evJoin, cudaEventDisableTiming);
        cudaGetSymbolAddress(&flagsPtr, g_flags);
        cudaFuncSetAttribute(gemm_xw_hmma, cudaFuncAttributeMaxDynamicSharedMemorySize, SM1_TOT);
        cudaFuncSetAttribute(lstm_rec_v9, cudaFuncAttributeMaxDynamicSharedMemorySize, SM2_TOT);
    }

    cudaMemsetAsync(flagsPtr, 0, sizeof(unsigned int) * K_ * 8, 0);

    cudaEventRecord(evFork, 0);
    cudaStreamWaitEvent(s2, evFork, 0);

    lstm_rec_v9<<<K_ * 4, 512, SM2_TOT, s2>>>(U, out);

    dim3 g1(8, 128, 8);
    gemm_xw_hmma<<<g1, 256, SM1_TOT, 0>>>(x, W, b);

    cudaEventRecord(evJoin, s2);
    cudaStreamWaitEvent(0, evJoin, 0);
}